// round 8
// baseline (speedup 1.0000x reference)
#include <cuda_runtime.h>

// Hybrid segment-sum: out[index[r], :] += src[r, :].
// Rows [0, rsplit):       streaming scatter (sequential src read, red.v4 into
//                         the L2-resident output)  -> loads the L2/atomic pipe.
// Rows [rsplit, nrows):   bucket gather-reduce     -> loads DRAM random-read.
// Both paths run CONCURRENTLY in one kernel (Bresenham-interleaved blocks) and
// accumulate via red.global.add.v4 into a pre-zeroed output, so the DRAM and
// LTS bottlenecks overlap instead of serializing.

#define CAP      64
#define MAX_SEG  65536
#define MAX_ROWS 1310720
#define SPLIT_NUM 7        // scatter fraction = 7/16 of rows
#define SPLIT_DEN 16

__device__ int g_ov_cnt;
__device__ int g_cnt[MAX_SEG];            // zero at load; reset by main kernel
__device__ int g_bucket[MAX_SEG * CAP];
__device__ int g_ovr[MAX_ROWS];           // overflow row ids
__device__ int g_ovs[MAX_ROWS];           // overflow seg ids

// Per-warp index-width detection: an int32 array (values in [0,nseg)) read
// as int64 gives huge values with overwhelming probability; the 128B probed
// stays in L1/L2 so recomputing per warp is ~free.
__device__ __forceinline__ bool detect_is64(const void* __restrict__ idx,
                                            int nseg) {
    const long long* p = (const long long*)idx;
    int lane = threadIdx.x & 31;
    long long v = __ldg(p + (lane & 15));
    int ok = (v >= 0 && v < (long long)nseg);
    return __all_sync(0xffffffffu, ok);
}

__device__ __forceinline__ void red_add_v4(float* dst, float4 v) {
    asm volatile("red.global.add.v4.f32 [%0], {%1, %2, %3, %4};"
                 :: "l"(dst), "f"(v.x), "f"(v.y), "f"(v.z), "f"(v.w)
                 : "memory");
}

// ------------------------------------------- K1: zero out + bin gather rows
__global__ __launch_bounds__(256)
void prep_kernel(const void* __restrict__ idx, float4* __restrict__ out,
                 int nrows, int nseg, int rsplit) {
    bool is64 = detect_is64(idx, nseg);
    int t      = blockIdx.x * blockDim.x + threadIdx.x;
    int nthr   = gridDim.x * blockDim.x;
    if (t == 0) g_ov_cnt = 0;

    // zero the poisoned output (nseg*16 float4s), grid-stride
    int nout4 = nseg * 16;
    for (int i = t; i < nout4; i += nthr)
        out[i] = make_float4(0.f, 0.f, 0.f, 0.f);

    // bin rows [rsplit, nrows): 4 consecutive rows per thread (rsplit % 4 == 0)
    int ngr = nrows - rsplit;                 // gather rows
    int q   = t;                              // quad id
    int base = rsplit + q * 4;
    if (base + 3 < nrows) {
        int ss[4];
        if (is64) {
            const longlong2* p = (const longlong2*)idx;
            longlong2 a = __ldg(p + (long long)base / 2);
            longlong2 b = __ldg(p + (long long)base / 2 + 1);
            ss[0] = (int)a.x; ss[1] = (int)a.y;
            ss[2] = (int)b.x; ss[3] = (int)b.y;
        } else {
            int4 a = __ldg((const int4*)idx + base / 4);
            ss[0] = a.x; ss[1] = a.y; ss[2] = a.z; ss[3] = a.w;
        }
        #pragma unroll
        for (int k = 0; k < 4; k++) {
            int rank = atomicAdd(&g_cnt[ss[k]], 1);
            if (rank < CAP) g_bucket[ss[k] * CAP + rank] = base + k;
            else {
                int o = atomicAdd(&g_ov_cnt, 1);
                g_ovr[o] = base + k; g_ovs[o] = ss[k];
            }
        }
    } else if (base < nrows) {
        for (int r = base; r < nrows; r++) {
            int seg = is64 ? (int)__ldg((const long long*)idx + r)
                           : __ldg((const int*)idx + r);
            int rank = atomicAdd(&g_cnt[seg], 1);
            if (rank < CAP) g_bucket[seg * CAP + rank] = r;
            else {
                int o = atomicAdd(&g_ov_cnt, 1);
                g_ovr[o] = r; g_ovs[o] = seg;
            }
        }
    }
    (void)ngr;
}

// ------------------------------------------- K2: fused gather + scatter
// Gather block: 8 warps, one segment per warp; half-warp float4 scheme,
//   8 rows (2KB) in flight, id prefetch; final 256B red.v4 accumulate.
// Scatter block: one float4 chunk per thread; sequential src read (__ldcs),
//   red.v4 into the L2-resident output.
__global__ __launch_bounds__(256)
void main_kernel(const float4* __restrict__ src,
                 const void* __restrict__ idx,
                 float4* __restrict__ out,
                 int nseg, int rsplit, int G, int T) {
    int b = blockIdx.x;
    long long gb = (long long)b * G / T;
    bool is_gather = ((long long)(b + 1) * G / T) > gb;

    if (is_gather) {
        int w = (int)gb * 8 + (threadIdx.x >> 5);
        int lane = threadIdx.x & 31;
        if (w >= nseg) return;
        int half = lane >> 4;
        int c    = lane & 15;

        int n = g_cnt[w];
        int m = (n < CAP) ? n : CAP;
        const int* bkt = g_bucket + w * CAP;

        float4 acc = make_float4(0.f, 0.f, 0.f, 0.f);
        int j = 0;
        int ids[8];
        if (m >= 8) {
            #pragma unroll
            for (int k = 0; k < 8; k++) ids[k] = __ldg(&bkt[k]);
        }
        for (; j + 16 <= m; j += 8) {
            int nid[8];
            #pragma unroll
            for (int k = 0; k < 8; k++) nid[k] = __ldg(&bkt[j + 8 + k]);
            float4 v[4];
            #pragma unroll
            for (int k = 0; k < 4; k++)
                v[k] = __ldcs(src + (long long)ids[half * 4 + k] * 16 + c);
            #pragma unroll
            for (int k = 0; k < 4; k++) {
                acc.x += v[k].x; acc.y += v[k].y;
                acc.z += v[k].z; acc.w += v[k].w;
            }
            #pragma unroll
            for (int k = 0; k < 8; k++) ids[k] = nid[k];
        }
        if (j + 8 <= m) {
            float4 v[4];
            #pragma unroll
            for (int k = 0; k < 4; k++)
                v[k] = __ldcs(src + (long long)ids[half * 4 + k] * 16 + c);
            #pragma unroll
            for (int k = 0; k < 4; k++) {
                acc.x += v[k].x; acc.y += v[k].y;
                acc.z += v[k].z; acc.w += v[k].w;
            }
            j += 8;
        }
        for (; j + 2 <= m; j += 2) {
            int id = __ldg(&bkt[j + half]);
            float4 v = __ldcs(src + (long long)id * 16 + c);
            acc.x += v.x; acc.y += v.y; acc.z += v.z; acc.w += v.w;
        }
        if (j < m && half == 0) {
            int id = __ldg(&bkt[j]);
            float4 v = __ldcs(src + (long long)id * 16 + c);
            acc.x += v.x; acc.y += v.y; acc.z += v.z; acc.w += v.w;
        }
        if (n > CAP) {      // exact overflow path (empty for uniform indices)
            int tot = *(volatile int*)&g_ov_cnt;
            for (int o = 0; o < tot; o++) {
                if (__ldg(&g_ovs[o]) == w && half == 0) {
                    int id = __ldg(&g_ovr[o]);
                    float4 v = __ldcs(src + (long long)id * 16 + c);
                    acc.x += v.x; acc.y += v.y; acc.z += v.z; acc.w += v.w;
                }
            }
        }

        acc.x += __shfl_xor_sync(0xffffffffu, acc.x, 16);
        acc.y += __shfl_xor_sync(0xffffffffu, acc.y, 16);
        acc.z += __shfl_xor_sync(0xffffffffu, acc.z, 16);
        acc.w += __shfl_xor_sync(0xffffffffu, acc.w, 16);

        if (lane == 0) g_cnt[w] = 0;          // clean for the next launch
        if (half == 0)
            red_add_v4((float*)(out + (long long)w * 16 + c), acc);
    } else {
        // ---- scatter path: chunk = row*16 + c over rows [0, rsplit)
        int sid = b - (int)gb;
        long long chunk = (long long)sid * 256 + threadIdx.x;
        long long nch = (long long)rsplit * 16;
        if (chunk >= nch) return;

        int r = (int)(chunk >> 4);
        int c = (int)(chunk & 15);
        bool is64 = detect_is64(idx, nseg);
        int seg = is64 ? (int)__ldg((const long long*)idx + r)
                       : __ldg((const int*)idx + r);
        float4 v = __ldcs(src + chunk);
        red_add_v4((float*)(out + (long long)seg * 16 + c), v);
    }
}

// ----------------------------------------------------------------
extern "C" void kernel_launch(void* const* d_in, const int* in_sizes, int n_in,
                              void* d_out, int out_size) {
    const float4* src = (const float4*)d_in[0];
    const void*   idx = d_in[1];
    float4*       out = (float4*)d_out;

    int nrows = in_sizes[0] / 64;   // 1,250,000
    int nseg  = out_size / 64;      // 50,000

    int rsplit = (int)(((long long)nrows * SPLIT_NUM / SPLIT_DEN) & ~3LL);

    // prep grid: cover max(bin quads, zero work)
    int bin_quads = (nrows - rsplit + 3) / 4;
    int zero_work = (nseg * 16 + 255) / 256 * 256;  // threads needed if 1 f4/thr
    int prep_thr  = bin_quads > zero_work ? bin_quads : zero_work;
    prep_kernel<<<(prep_thr + 255) / 256, 256>>>(idx, out, nrows, nseg, rsplit);

    int G = (nseg + 7) / 8;                          // gather blocks
    long long chunks = (long long)rsplit * 16;
    int S = (int)((chunks + 255) / 256);             // scatter blocks
    int T = G + S;
    main_kernel<<<T, 256>>>(src, idx, out, nseg, rsplit, G, T);
}

// round 10
// speedup vs baseline: 1.2150x; 1.2150x over previous
#include <cuda_runtime.h>

// Segment-sum out[index[r], :] += src[r, :] (src (nrows,64) fp32 -> out (nseg,64)).
//
// ONE persistent kernel (4 blocks/SM, co-residency guaranteed by
// __launch_bounds__(256,4) and grid = 4 * SM count):
//   phase 1: grid-stride binning  rank=atomicAdd(cnt[seg]); bucket[seg*64+rank]=r
//   ---- software grid barrier (two-counter, deadlock-free) ----
//   phase 2: warp-strided gather-reduce, one segment at a time per warp;
//            half-warp float4 scheme, 8 rows (2KB) in flight, plain 256B store.
// Overflow beyond CAP rows/segment goes to an exact side list, consumed in
// phase 2 -> correct for any index distribution (empty for uniform indices).
// R8 post-mortem: hybrid scatter+gather mixing collapsed DRAM to 48% -> revert
// to pure bucket-gather; this round removes the 2nd launch (+~4.5us floor/gap).

#define CAP      64
#define MAX_SEG  65536
#define MAX_ROWS 1310720

__device__ int g_ov_cnt;                  // static 0; reset by last block
__device__ unsigned g_c1, g_c2;           // barrier counters; reset by last block
__device__ int g_cnt[MAX_SEG];            // zero at load; reset in phase 2
__device__ int g_bucket[MAX_SEG * CAP];
__device__ int g_ovr[MAX_ROWS];
__device__ int g_ovs[MAX_ROWS];

// Per-warp index-width detection: an int32 array (values in [0,nseg)) read
// as int64 gives huge values with overwhelming probability; the 128B probed
// stays in L1/L2 so recomputing per warp is ~free.
__device__ __forceinline__ bool detect_is64(const void* __restrict__ idx,
                                            int nseg) {
    const long long* p = (const long long*)idx;
    int lane = threadIdx.x & 31;
    long long v = __ldg(p + (lane & 15));
    int ok = (v >= 0 && v < (long long)nseg);
    return __all_sync(0xffffffffu, ok);
}

__device__ __forceinline__ void bin_one(int seg, int row) {
    int rank = atomicAdd(&g_cnt[seg], 1);
    if (rank < CAP) {
        g_bucket[seg * CAP + rank] = row;
    } else {
        int o = atomicAdd(&g_ov_cnt, 1);
        g_ovr[o] = row;
        g_ovs[o] = seg;
    }
}

__global__ __launch_bounds__(256, 4)
void fused_kernel(const float4* __restrict__ src,
                  const void* __restrict__ idx,
                  float4* __restrict__ out,
                  int nrows, int nseg) {
    const bool is64 = detect_is64(idx, nseg);
    const int t    = blockIdx.x * 256 + threadIdx.x;
    const int nthr = gridDim.x * 256;

    // ---------------- phase 1: bin rows by segment (4 rows / iteration)
    const int nquads = nrows >> 2;
    for (int q = t; q < nquads; q += nthr) {
        int base = q * 4;
        int ss[4];
        if (is64) {
            const longlong2* p = (const longlong2*)idx;
            longlong2 a = __ldg(p + (long long)q * 2);
            longlong2 b = __ldg(p + (long long)q * 2 + 1);
            ss[0] = (int)a.x; ss[1] = (int)a.y;
            ss[2] = (int)b.x; ss[3] = (int)b.y;
        } else {
            int4 a = __ldg((const int4*)idx + q);
            ss[0] = a.x; ss[1] = a.y; ss[2] = a.z; ss[3] = a.w;
        }
        #pragma unroll
        for (int k = 0; k < 4; k++) bin_one(ss[k], base + k);
    }
    {   // tail rows (nrows % 4)
        int tail = nrows & 3;
        if (t < tail) {
            int r = nrows - tail + t;
            int seg = is64 ? (int)__ldg((const long long*)idx + r)
                           : __ldg((const int*)idx + r);
            bin_one(seg, r);
        }
    }

    // ---------------- grid barrier (all blocks co-resident by construction)
    __syncthreads();
    if (threadIdx.x == 0) {
        __threadfence();
        atomicAdd(&g_c1, 1u);
        while (atomicAdd(&g_c1, 0u) < (unsigned)gridDim.x) __nanosleep(64);
    }
    __syncthreads();
    __threadfence();

    // ---------------- phase 2: warp-strided gather-reduce
    const int nwarps = nthr >> 5;
    const int wg     = t >> 5;
    const int lane   = threadIdx.x & 31;
    const int half   = lane >> 4;
    const int c      = lane & 15;

    for (int w = wg; w < nseg; w += nwarps) {
        int n = g_cnt[w];
        int m = (n < CAP) ? n : CAP;
        const int* bkt = g_bucket + w * CAP;

        float4 acc = make_float4(0.f, 0.f, 0.f, 0.f);
        int j = 0;
        int ids[8];
        if (m >= 8) {
            #pragma unroll
            for (int k = 0; k < 8; k++) ids[k] = __ldg(&bkt[k]);
        }
        for (; j + 16 <= m; j += 8) {
            int nid[8];
            #pragma unroll
            for (int k = 0; k < 8; k++) nid[k] = __ldg(&bkt[j + 8 + k]);
            float4 v[4];
            #pragma unroll
            for (int k = 0; k < 4; k++)
                v[k] = __ldcs(src + (long long)ids[half * 4 + k] * 16 + c);
            #pragma unroll
            for (int k = 0; k < 4; k++) {
                acc.x += v[k].x; acc.y += v[k].y;
                acc.z += v[k].z; acc.w += v[k].w;
            }
            #pragma unroll
            for (int k = 0; k < 8; k++) ids[k] = nid[k];
        }
        if (j + 8 <= m) {          // last full batch: ids already in registers
            float4 v[4];
            #pragma unroll
            for (int k = 0; k < 4; k++)
                v[k] = __ldcs(src + (long long)ids[half * 4 + k] * 16 + c);
            #pragma unroll
            for (int k = 0; k < 4; k++) {
                acc.x += v[k].x; acc.y += v[k].y;
                acc.z += v[k].z; acc.w += v[k].w;
            }
            j += 8;
        }
        for (; j + 2 <= m; j += 2) {   // pair tail: half h takes row j+h
            int id = __ldg(&bkt[j + half]);
            float4 v = __ldcs(src + (long long)id * 16 + c);
            acc.x += v.x; acc.y += v.y; acc.z += v.z; acc.w += v.w;
        }
        if (j < m && half == 0) {      // single tail: half 0 only
            int id = __ldg(&bkt[j]);
            float4 v = __ldcs(src + (long long)id * 16 + c);
            acc.x += v.x; acc.y += v.y; acc.z += v.z; acc.w += v.w;
        }

        if (n > CAP) {   // exact overflow path (empty for uniform indices)
            int tot = *(volatile int*)&g_ov_cnt;
            for (int o = 0; o < tot; o++) {
                if (__ldg(&g_ovs[o]) == w && half == 0) {
                    int id = __ldg(&g_ovr[o]);
                    float4 v = __ldcs(src + (long long)id * 16 + c);
                    acc.x += v.x; acc.y += v.y; acc.z += v.z; acc.w += v.w;
                }
            }
        }

        acc.x += __shfl_xor_sync(0xffffffffu, acc.x, 16);
        acc.y += __shfl_xor_sync(0xffffffffu, acc.y, 16);
        acc.z += __shfl_xor_sync(0xffffffffu, acc.z, 16);
        acc.w += __shfl_xor_sync(0xffffffffu, acc.w, 16);

        if (lane == 0) g_cnt[w] = 0;             // clean for the next launch
        if (half == 0)
            out[(long long)w * 16 + c] = acc;    // 16 lanes x 16B = 256B
    }

    // ---------------- cleanup: last-exiting block resets barrier state.
    // Safe: done==gridDim requires EVERY block to have passed the c1 spin
    // and finished phase 2, so no block can still be reading g_c1/g_ov_cnt.
    __syncthreads();
    if (threadIdx.x == 0) {
        __threadfence();
        unsigned done = atomicAdd(&g_c2, 1u) + 1u;
        if (done == (unsigned)gridDim.x) {
            g_ov_cnt = 0;
            atomicExch(&g_c1, 0u);
            atomicExch(&g_c2, 0u);
        }
    }
}

// ----------------------------------------------------------------
extern "C" void kernel_launch(void* const* d_in, const int* in_sizes, int n_in,
                              void* d_out, int out_size) {
    const float4* src = (const float4*)d_in[0];
    const void*   idx = d_in[1];
    float4*       out = (float4*)d_out;

    int nrows = in_sizes[0] / 64;   // 1,250,000
    int nseg  = out_size / 64;      // 50,000

    static int nsm = 0;             // host-side cache; queried once
    if (nsm == 0) {
        cudaDeviceProp prop;
        cudaGetDeviceProperties(&prop, 0);
        nsm = prop.multiProcessorCount;     // 148 (B300) / 152 (GB300)
    }
    int grid = nsm * 4;             // 4 blocks/SM, co-resident by launch_bounds

    fused_kernel<<<grid, 256>>>(src, idx, out, nrows, nseg);
}

// round 11
// speedup vs baseline: 1.3135x; 1.0811x over previous
#include <cuda_runtime.h>

// Segment-sum out[index[r], :] += src[r, :] (src (nrows,64) fp32 -> out (nseg,64)).
//
// 2-kernel pipeline (persistent fusion reverted: R10 showed reg-union -> occ 48%
// -> DRAM 50%; the gather phase needs 2048 thr/SM @ 32 regs):
//   K1 bin:    rank = atomicAdd(cnt[seg]); bucket[seg*64+rank] = r
//              (4 rows/thread, vectorized idx loads, per-warp width detect)
//   K2 reduce: grid-stride warps over segments, grid = SMs*8 blocks
//              (__launch_bounds__(256,8) -> 100%% theoretical occupancy, no
//              wave transitions); half-warp float4 gather, 8 rows in flight,
//              PREDICATED 8-wide tail batch (no serial pair loads);
//              one plain 256B store per segment.
// Overflow beyond CAP rows/segment goes to an exact side list (capacity =
// all rows), consumed in reduce -> correct for any index distribution.

#define CAP      64
#define MAX_SEG  65536
#define MAX_ROWS 1310720

__device__ int g_ov_cnt;
__device__ int g_cnt[MAX_SEG];            // zero at load; reset by reduce
__device__ int g_bucket[MAX_SEG * CAP];
__device__ int g_ovr[MAX_ROWS];           // overflow row ids
__device__ int g_ovs[MAX_ROWS];           // overflow seg ids

// Per-warp index-width detection: an int32 array (values in [0,nseg)) read
// as int64 gives huge values with overwhelming probability; the 128B probed
// stays in L1/L2 so recomputing per warp is ~free.
__device__ __forceinline__ bool detect_is64(const void* __restrict__ idx,
                                            int nseg) {
    const long long* p = (const long long*)idx;
    int lane = threadIdx.x & 31;
    long long v = __ldg(p + (lane & 15));
    int ok = (v >= 0 && v < (long long)nseg);
    return __all_sync(0xffffffffu, ok);
}

__device__ __forceinline__ void bin_one(int seg, int row) {
    int rank = atomicAdd(&g_cnt[seg], 1);
    if (rank < CAP) {
        g_bucket[seg * CAP + rank] = row;
    } else {
        int o = atomicAdd(&g_ov_cnt, 1);
        g_ovr[o] = row;
        g_ovs[o] = seg;
    }
}

// ---------------------------------------------------- K1: bin rows by segment
// Thread t owns rows [4t, 4t+4): one int4 (int32 idx) or two longlong2
// (int64 idx) vector loads, then 4 batched atomics+stores.
__global__ __launch_bounds__(256)
void bin_kernel(const void* __restrict__ idx, int nrows, int nseg) {
    bool is64 = detect_is64(idx, nseg);
    if (blockIdx.x == 0 && threadIdx.x == 0) g_ov_cnt = 0;

    int t = blockIdx.x * blockDim.x + threadIdx.x;
    int base = t * 4;

    if (base + 3 < nrows) {
        int ss[4];
        if (is64) {
            const longlong2* p = (const longlong2*)idx;
            longlong2 a = __ldg(p + t * 2);
            longlong2 b = __ldg(p + t * 2 + 1);
            ss[0] = (int)a.x; ss[1] = (int)a.y;
            ss[2] = (int)b.x; ss[3] = (int)b.y;
        } else {
            int4 a = __ldg((const int4*)idx + t);
            ss[0] = a.x; ss[1] = a.y; ss[2] = a.z; ss[3] = a.w;
        }
        #pragma unroll
        for (int k = 0; k < 4; k++) bin_one(ss[k], base + k);
    } else {
        for (int r = base; r < nrows; r++) {
            int seg = is64 ? (int)__ldg((const long long*)idx + r)
                           : __ldg((const int*)idx + r);
            bin_one(seg, r);
        }
    }
}

// ---------------------------------------------------- K2: gather-reduce
// Grid-stride warps over segments. Half-warp scheme: lanes 0-15 own rows
// j..j+3 of each 8-row batch, lanes 16-31 own rows j+4..j+7; each lane
// loads float4 (16 lanes x 16B = 256B/row, fully coalesced). Tail handled
// by ONE predicated 8-wide batch. src read with __ldcs (evict-first).
__global__ __launch_bounds__(256, 8)
void reduce_kernel(const float4* __restrict__ src,
                   float4* __restrict__ out, int nseg) {
    const int nwarps = (gridDim.x * blockDim.x) >> 5;
    const int wg     = (blockIdx.x * blockDim.x + threadIdx.x) >> 5;
    const int lane   = threadIdx.x & 31;
    const int half   = lane >> 4;
    const int c      = lane & 15;

    for (int w = wg; w < nseg; w += nwarps) {
        int n = __ldg(&g_cnt[w]);
        int m = (n < CAP) ? n : CAP;
        const int* bkt = g_bucket + w * CAP;

        float4 acc = make_float4(0.f, 0.f, 0.f, 0.f);
        int j = 0;

        int ids[8];
        if (m >= 8) {
            #pragma unroll
            for (int k = 0; k < 8; k++) ids[k] = __ldg(&bkt[k]);
        }
        for (; j + 16 <= m; j += 8) {
            int nid[8];
            #pragma unroll
            for (int k = 0; k < 8; k++) nid[k] = __ldg(&bkt[j + 8 + k]);
            float4 v[4];
            #pragma unroll
            for (int k = 0; k < 4; k++)
                v[k] = __ldcs(src + (long long)ids[half * 4 + k] * 16 + c);
            #pragma unroll
            for (int k = 0; k < 4; k++) {
                acc.x += v[k].x; acc.y += v[k].y;
                acc.z += v[k].z; acc.w += v[k].w;
            }
            #pragma unroll
            for (int k = 0; k < 8; k++) ids[k] = nid[k];
        }
        if (j + 8 <= m) {          // last full batch: ids already in registers
            float4 v[4];
            #pragma unroll
            for (int k = 0; k < 4; k++)
                v[k] = __ldcs(src + (long long)ids[half * 4 + k] * 16 + c);
            #pragma unroll
            for (int k = 0; k < 4; k++) {
                acc.x += v[k].x; acc.y += v[k].y;
                acc.z += v[k].z; acc.w += v[k].w;
            }
            j += 8;
        }
        // Predicated tail: remaining rem = m - j in [0, 8); all loads issued
        // independently in one batch (no serial pair round-trips).
        #pragma unroll
        for (int k = 0; k < 4; k++) {
            int rowk = j + half * 4 + k;
            if (rowk < m) {
                int id = __ldg(&bkt[rowk]);
                float4 v = __ldcs(src + (long long)id * 16 + c);
                acc.x += v.x; acc.y += v.y; acc.z += v.z; acc.w += v.w;
            }
        }

        if (n > CAP) {   // exact overflow path (empty for uniform indices)
            int tot = *(volatile int*)&g_ov_cnt;
            for (int o = 0; o < tot; o++) {
                if (__ldg(&g_ovs[o]) == w && half == 0) {
                    int id = __ldg(&g_ovr[o]);
                    float4 v = __ldcs(src + (long long)id * 16 + c);
                    acc.x += v.x; acc.y += v.y; acc.z += v.z; acc.w += v.w;
                }
            }
        }

        // Combine halves: lanes l and l^16 hold partials of the same columns.
        acc.x += __shfl_xor_sync(0xffffffffu, acc.x, 16);
        acc.y += __shfl_xor_sync(0xffffffffu, acc.y, 16);
        acc.z += __shfl_xor_sync(0xffffffffu, acc.z, 16);
        acc.w += __shfl_xor_sync(0xffffffffu, acc.w, 16);

        if (lane == 0) g_cnt[w] = 0;           // clean for the next launch
        if (half == 0)
            out[(long long)w * 16 + c] = acc;  // 16 lanes x 16B = 256B store
    }
}

// ----------------------------------------------------------------
extern "C" void kernel_launch(void* const* d_in, const int* in_sizes, int n_in,
                              void* d_out, int out_size) {
    const float4* src = (const float4*)d_in[0];
    const void*   idx = d_in[1];
    float4*       out = (float4*)d_out;

    int nrows = in_sizes[0] / 64;   // 1,250,000
    int nseg  = out_size / 64;      // 50,000

    static int nsm = 0;             // host-side cache; queried once
    if (nsm == 0) {
        cudaDeviceProp prop;
        cudaGetDeviceProperties(&prop, 0);
        nsm = prop.multiProcessorCount;     // 148 (B300) / 152 (GB300)
    }

    int bin_threads = (nrows + 3) / 4;
    bin_kernel<<<(bin_threads + 255) / 256, 256>>>(idx, nrows, nseg);

    // 8 co-resident 256-thread blocks per SM (100% theoretical occupancy),
    // grid-stride over segments: no wave transitions, no tail waves.
    reduce_kernel<<<nsm * 8, 256>>>(src, out, nseg);
}